// round 11
// baseline (speedup 1.0000x reference)
#include <cuda_runtime.h>
#include <cuda_bf16.h>
#include <math.h>

// ---------------------------------------------------------------------------
// HybridConv: out[n] = MLP(RBF(sigmoid(dot(data[n], conv_w) + conv_b)))
// out = f(t), t = 2*sigmoid(logit)-1 = tanh(logit/2), f analytic on [-1,1].
// Build (1 warp): f at 32 Chebyshev nodes -> DCT -> Chebyshev -> monomial via
// COMPILE-TIME integer T_k matrix. Main: WARP-BLOCKED streaming — each warp
// owns 128 consecutive patches; every LDG.128 is 512B-contiguous (4 wavefronts
// vs 16 for the old 64B-strided layout) and stores are coalesced STG.32.
// Degree-11 Horner in fma.rn.f32x2 (2 patches/instr).
// ---------------------------------------------------------------------------

#define NCOEF 12   // monomial degree 11
#define BASIS 8
#define HIDDEN 16

__device__ float g_coef[NCOEF];

// Chebyshev T_k power-basis coefficients (exact integers), T[k][j] = coeff of x^j
__device__ __constant__ float c_T[NCOEF][NCOEF] = {
    {   1,    0,    0,    0,     0,     0,    0,    0,     0,     0,    0,    0},
    {   0,    1,    0,    0,     0,     0,    0,    0,     0,     0,    0,    0},
    {  -1,    0,    2,    0,     0,     0,    0,    0,     0,     0,    0,    0},
    {   0,   -3,    0,    4,     0,     0,    0,    0,     0,     0,    0,    0},
    {   1,    0,   -8,    0,     8,     0,    0,    0,     0,     0,    0,    0},
    {   0,    5,    0,  -20,     0,    16,    0,    0,     0,     0,    0,    0},
    {  -1,    0,   18,    0,   -48,     0,   32,    0,     0,     0,    0,    0},
    {   0,   -7,    0,   56,     0,  -112,    0,   64,     0,     0,    0,    0},
    {   1,    0,  -32,    0,   160,     0, -256,    0,   128,     0,    0,    0},
    {   0,    9,    0, -120,     0,   432,    0, -576,     0,   256,    0,    0},
    {  -1,    0,   50,    0,  -400,     0, 1120,    0, -1280,     0,  512,    0},
    {   0,  -11,    0,  220,     0, -1232,    0, 2816,     0, -2816,    0, 1024}
};

#define FMA2(d, a, b, c) \
    asm("fma.rn.f32x2 %0, %1, %2, %3;" \
        : "=l"(d) : "l"(a), "l"(b), "l"(c))
#define PACK2(d, lo, hi) \
    asm("mov.b64 %0, {%1, %2};" : "=l"(d) : "f"(lo), "f"(hi))
#define UNPACK2(lo, hi, s) \
    asm("mov.b64 {%0, %1}, %2;" : "=f"(lo), "=f"(hi) : "l"(s))

__device__ __forceinline__ float fast_tanh(float x) {
    float y;
    asm("tanh.approx.f32 %0, %1;" : "=f"(y) : "f"(x));
    return y;
}

// ---- build: one warp. nodes -> DCT -> monomial (constant matrix) ----------
__global__ void build_coef_kernel(const float* __restrict__ basis,
                                  const float* __restrict__ w1,
                                  const float* __restrict__ b1,
                                  const float* __restrict__ w2,
                                  const float* __restrict__ b2) {
    __shared__ float s_e[32];
    const int lane = threadIdx.x;          // 0..31

    // node: t_j = cos(pi*(2j+1)/64), act a = (1+t)/2
    float t_node = cospif((float)(2 * lane + 1) * (1.0f / 64.0f));
    float a = 0.5f + 0.5f * t_node;

    // f(a): RBF feats -> MLP (precise float)
    float feats[BASIS];
#pragma unroll
    for (int j = 0; j < BASIS; j++) {
        float s = 0.0f;
#pragma unroll
        for (int k = 0; k < 4; k++) {
            float d = a - basis[j * 4 + k];
            s = fmaf(d, d, s);
        }
        feats[j] = expf(-s);               // GAMMA = 1
    }
    float fv = b2[0];
#pragma unroll
    for (int i = 0; i < HIDDEN; i++) {
        float p = b1[i];
#pragma unroll
        for (int j = 0; j < BASIS; j++)
            p = fmaf(feats[j], w1[j * HIDDEN + i], p);
        fv = fmaf(tanhf(p), w2[i], fv);
    }

    // DCT: e_k = (1/16) sum_j f_j cos(pi*k*(2j+1)/64); lane = k. Full warp.
    float ck = 0.0f;
#pragma unroll 4
    for (int j = 0; j < 32; j++) {
        float fj = __shfl_sync(0xFFFFFFFFu, fv, j);
        float w  = cospif((float)(lane * (2 * j + 1)) * (1.0f / 64.0f));
        ck = fmaf(fj, w, ck);
    }
    ck *= (1.0f / 16.0f);
    if (lane == 0) ck *= 0.5f;             // e_0 = c_0/2
    s_e[lane] = ck;
    __syncwarp();

    // monomial a_j = sum_k e_k * T[k][j]  (lane = j), constant matrix
    if (lane < NCOEF) {
        float acc = 0.0f;
#pragma unroll
        for (int k = 0; k < NCOEF; k++)
            acc = fmaf(s_e[k], c_T[k][lane], acc);
        g_coef[lane] = acc;
    }
}

// ---- main streaming pass: warp-blocked, fully coalesced -------------------
__global__ void __launch_bounds__(256, 6)
hybridconv_main_kernel(const float4* __restrict__ data,
                       const float* __restrict__ conv_w,
                       const float* __restrict__ conv_b,
                       float* __restrict__ out, int nChunks, int n) {
    // load + pack coefficient pairs ONCE (warp-uniform)
    unsigned long long c2[NCOEF];
#pragma unroll
    for (int k = 0; k < NCOEF; k++) {
        float ck = g_coef[k];
        PACK2(c2[k], ck, ck);
    }

    const float w0 = conv_w[0], w1 = conv_w[1];
    const float w2 = conv_w[2], w3 = conv_w[3];
    const float bb = conv_b[0];

    const int gid    = blockIdx.x * blockDim.x + threadIdx.x;
    const int warpId = gid >> 5;
    const int lane   = gid & 31;
    const int nWarps = (gridDim.x * blockDim.x) >> 5;

    // Each warp owns 128 consecutive patches per chunk. Thread t handles
    // patches base+t, base+32+t, base+64+t, base+96+t: every LDG.128 is
    // 512B contiguous across the warp; stores are coalesced STG.32.
    for (int chunk = warpId; chunk < nChunks; chunk += nWarps) {
        const int base = (chunk << 7) + lane;
        const float4* p = data + base;
        float4 v0 = __ldcs(p);
        float l0 = fmaf(v0.x, w0, fmaf(v0.y, w1, fmaf(v0.z, w2, fmaf(v0.w, w3, bb))));
        float4 v1 = __ldcs(p + 32);
        float l1 = fmaf(v1.x, w0, fmaf(v1.y, w1, fmaf(v1.z, w2, fmaf(v1.w, w3, bb))));
        float4 v2 = __ldcs(p + 64);
        float l2 = fmaf(v2.x, w0, fmaf(v2.y, w1, fmaf(v2.z, w2, fmaf(v2.w, w3, bb))));
        float4 v3 = __ldcs(p + 96);
        float l3 = fmaf(v3.x, w0, fmaf(v3.y, w1, fmaf(v3.z, w2, fmaf(v3.w, w3, bb))));

        // t = 2*sigmoid(l)-1 = tanh(l/2): one MUFU each
        float t0 = fast_tanh(0.5f * l0);
        float t1 = fast_tanh(0.5f * l1);
        float t2 = fast_tanh(0.5f * l2);
        float t3 = fast_tanh(0.5f * l3);

        unsigned long long tA, tB;
        PACK2(tA, t0, t1);
        PACK2(tB, t2, t3);

        // Horner, two f32x2 chains: 1 FMA2 per level per pair
        unsigned long long hA = c2[NCOEF - 1], hB = c2[NCOEF - 1];
#pragma unroll
        for (int k = NCOEF - 2; k >= 0; k--) {
            FMA2(hA, tA, hA, c2[k]);
            FMA2(hB, tB, hB, c2[k]);
        }

        float r0, r1, r2, r3;
        UNPACK2(r0, r1, hA);
        UNPACK2(r2, r3, hB);
        float* o = out + base;
        __stcs(o,      r0);
        __stcs(o + 32, r1);
        __stcs(o + 64, r2);
        __stcs(o + 96, r3);
    }

    // defensive tail for n % 128 != 0 (empty for N = 2^23)
    for (int k = (nChunks << 7) + gid; k < n; k += gridDim.x * blockDim.x) {
        float4 v = data[k];
        float l = fmaf(v.x, w0, fmaf(v.y, w1, fmaf(v.z, w2, fmaf(v.w, w3, bb))));
        float t = fast_tanh(0.5f * l);
        float h = g_coef[NCOEF - 1];
        for (int q = NCOEF - 2; q >= 0; q--)
            h = fmaf(t, h, g_coef[q]);
        out[k] = h;
    }
}

extern "C" void kernel_launch(void* const* d_in, const int* in_sizes, int n_in,
                              void* d_out, int out_size) {
    const float* data   = (const float*)d_in[0];   // [N, 2, 2]
    const float* conv_w = (const float*)d_in[1];   // [2, 2]
    const float* conv_b = (const float*)d_in[2];   // [1]
    const float* basis  = (const float*)d_in[3];   // [8, 4]
    const float* w1     = (const float*)d_in[4];   // [8, 16]
    const float* b1     = (const float*)d_in[5];   // [16]
    const float* w2     = (const float*)d_in[6];   // [16, 1]
    const float* b2     = (const float*)d_in[7];   // [1]

    const int n       = in_sizes[0] / 4;   // patches
    const int nChunks = n >> 7;            // 128-patch warp chunks

    build_coef_kernel<<<1, 32>>>(basis, w1, b1, w2, b2);

    // 912 blocks = exactly 6 CTAs/SM x 152 SMs -> single wave
    hybridconv_main_kernel<<<912, 256>>>(
        (const float4*)data, conv_w, conv_b, (float*)d_out, nChunks, n);
}